// round 4
// baseline (speedup 1.0000x reference)
#include <cuda_runtime.h>
#include <cuda_fp16.h>
#include <math.h>
#include <stdint.h>

#define Bb 8
#define Ss 1024
#define Dd 1024
#define Hh 16
#define HDIM 64
#define Ff 4096
#define Mm (Bb*Ss)

// ---------------------------------------------------------------------------
// Scratch (device globals). Pair tensors: [0..n) = hi plane, [n..2n) = lo.
// ---------------------------------------------------------------------------
__device__ __half g_qp [2*(size_t)Mm*Dd];
__device__ __half g_kp [2*(size_t)Mm*Dd];
__device__ __half g_vp [2*(size_t)Mm*Dd];
__device__ __half g_Qp [2*(size_t)Mm*Dd];
__device__ __half g_Kp [2*(size_t)Mm*Dd];
__device__ __half g_Vp [2*(size_t)Mm*Dd];
__device__ __half g_Vtp[2*(size_t)Bb*Hh*HDIM*Ss];
__device__ __half g_ctx[2*(size_t)Mm*Dd];
__device__ __half g_aop[2*(size_t)Mm*Dd];
__device__ __half g_Fp [2*(size_t)Mm*Ff];
__device__ __half g_Pp [2*(size_t)Bb*Hh*Ss*Ss];
__device__ __half g_WTp[2*(size_t)(4*Dd*Dd + Dd*Ff + Ff*Dd)];
__device__ float  g_S  [(size_t)Bb*Hh*Ss*Ss];
__device__ float  g_X  [(size_t)Mm*Dd];
__device__ float  g_ao [(size_t)Mm*Dd];
__device__ float  g_Z  [(size_t)Mm*Dd];

// ---------------------------------------------------------------------------
// PTX helpers (baseline sm_80+ features, valid on plain sm_103 target)
// ---------------------------------------------------------------------------
__device__ __forceinline__ uint32_t smem_u32(const void* p) {
    uint32_t a;
    asm("{ .reg .u64 t; cvta.to.shared.u64 t, %1; cvt.u32.u64 %0, t; }"
        : "=r"(a) : "l"(p));
    return a;
}
__device__ __forceinline__ void ldsm4(uint32_t& r0, uint32_t& r1, uint32_t& r2,
                                      uint32_t& r3, uint32_t addr) {
    asm volatile("ldmatrix.sync.aligned.m8n8.x4.shared.b16 {%0,%1,%2,%3}, [%4];"
                 : "=r"(r0), "=r"(r1), "=r"(r2), "=r"(r3) : "r"(addr));
}
__device__ __forceinline__ void mma16816(float* d, const uint32_t* a,
                                         const uint32_t* b) {
    asm volatile(
        "mma.sync.aligned.m16n8k16.row.col.f32.f16.f16.f32 "
        "{%0,%1,%2,%3}, {%4,%5,%6,%7}, {%8,%9}, {%0,%1,%2,%3};"
        : "+f"(d[0]), "+f"(d[1]), "+f"(d[2]), "+f"(d[3])
        : "r"(a[0]), "r"(a[1]), "r"(a[2]), "r"(a[3]), "r"(b[0]), "r"(b[1]));
}
__device__ __forceinline__ void cpa16(uint32_t dst, const void* src) {
    asm volatile("cp.async.cg.shared.global [%0], [%1], 16;"
                 :: "r"(dst), "l"(src) : "memory");
}
#define CP_COMMIT() asm volatile("cp.async.commit_group;" ::: "memory")
#define CP_WAIT(n)  asm volatile("cp.async.wait_group %0;" :: "n"(n) : "memory")

// fp32 pair split store: hi = f16(x), lo = f16(x - hi)
__device__ __forceinline__ void store_pair(__half* H, __half* L, size_t off,
                                           float2 v) {
    __half2 h = __floats2half2_rn(v.x, v.y);
    float2 hf = __half22float2(h);
    __half2 l = __floats2half2_rn(v.x - hf.x, v.y - hf.y);
    *(__half2*)(H + off) = h;
    *(__half2*)(L + off) = l;
}

// ---------------------------------------------------------------------------
// GEMM on pre-split fp16 pairs (fp32-equivalent accuracy):
//   C[128 x BN] = A[128,K] @ B[BN,K]^T, D = Ah*Bh + Al*Bh + Ah*Bl, fp32 acc.
//   Pure cp.async -> ldmatrix -> mma mainloop, 3-stage pipeline.
//   Batch via blockIdx.z: off = (z>>4)*s1 + (z&15)*s2 (elements, both planes).
//   EPI: 0=+bias  1=+bias,relu  2=scores(x/8+(1-mask)*-1e4)  3=plain
//   CFMT: 0 = fp32 out (C) ; 1 = fp16 pair out (CH/CL)
// ---------------------------------------------------------------------------
template<int BN, int EPI, int CFMT>
__global__ void __launch_bounds__(256, 1) gemm_ps(
    const __half* __restrict__ AH, const __half* __restrict__ AL,
    long long lda, long long a1, long long a2,
    const __half* __restrict__ BH, const __half* __restrict__ BL,
    long long ldb, long long b1, long long b2,
    float* __restrict__ C, __half* __restrict__ CH, __half* __restrict__ CL,
    long long ldc, long long c1, long long c2,
    const float* __restrict__ aux, int K)
{
    constexpr int MF = 4;                 // m16 frags per warp (m span 64)
    constexpr int NF = BN / 32;           // n8 frags per warp (n span BN/4)
    constexpr int NBI = BN / 64;          // B cp.async iters per plane
    constexpr int STAGE = 20480 + BN * 160;  // bytes per stage

    extern __shared__ char dsm[];

    const int tid = threadIdx.x, lane = tid & 31, wid = tid >> 5;
    const int zb = blockIdx.z >> 4, zh = blockIdx.z & 15;
    const int row0 = blockIdx.y * 128, col0 = blockIdx.x * BN;
    const int m0w = (wid >> 2) * 64, n0w = (wid & 3) * (BN / 4);

    const __half* Abh = AH + zb * a1 + zh * a2 + (size_t)row0 * lda;
    const __half* Abl = AL + zb * a1 + zh * a2 + (size_t)row0 * lda;
    const __half* Bbh = BH + zb * b1 + zh * b2 + (size_t)col0 * ldb;
    const __half* Bbl = BL + zb * b1 + zh * b2 + (size_t)col0 * ldb;
    float* Cb = C + zb * c1 + zh * c2;
    __half* CbH = CH + zb * c1 + zh * c2;
    __half* CbL = CL + zb * c1 + zh * c2;

    const uint32_t sbase = smem_u32(dsm);

    float acc[MF][NF][4];
#pragma unroll
    for (int i = 0; i < MF; i++)
#pragma unroll
        for (int j = 0; j < NF; j++)
#pragma unroll
            for (int k = 0; k < 4; k++) acc[i][j][k] = 0.f;

    auto issue = [&](int st, int k0) {
        uint32_t base = sbase + st * STAGE;
#pragma unroll
        for (int i = 0; i < 2; i++) {       // A: 128 rows x 4 16B-groups, x2
            int q = tid + i * 256;
            int r = q >> 2, g = q & 3;
            uint32_t d = base + r * 80 + g * 16;
            cpa16(d,         Abh + (size_t)r * lda + k0 + g * 8);
            cpa16(d + 10240, Abl + (size_t)r * lda + k0 + g * 8);
        }
#pragma unroll
        for (int i = 0; i < NBI; i++) {     // B: BN rows x 4 groups
            int q = tid + i * 256;
            int r = q >> 2, g = q & 3;
            uint32_t d = base + 20480 + r * 80 + g * 16;
            cpa16(d,           Bbh + (size_t)r * ldb + k0 + g * 8);
            cpa16(d + BN * 80, Bbl + (size_t)r * ldb + k0 + g * 8);
        }
        CP_COMMIT();
    };

    const int NC = K >> 5;
    issue(0, 0);
    if (NC > 1) issue(1, 32);

    for (int c = 0; c < NC; c++) {
        if (c + 1 < NC) CP_WAIT(1); else CP_WAIT(0);
        __syncthreads();
        if (c + 2 < NC) issue((c + 2) % 3, (c + 2) * 32);

        const uint32_t aAh = sbase + (c % 3) * STAGE;
        const uint32_t aAl = aAh + 10240;
        const uint32_t aBh = aAh + 20480;
        const uint32_t aBl = aBh + BN * 80;
#pragma unroll
        for (int kk = 0; kk < 32; kk += 16) {
            uint32_t ah[MF][4], al[MF][4], bh[NF][2], bl[NF][2];
#pragma unroll
            for (int mi = 0; mi < MF; mi++) {
                uint32_t ao = (uint32_t)((m0w + mi * 16 + (lane & 15)) * 40 +
                                         kk + ((lane >> 4) << 3)) * 2;
                ldsm4(ah[mi][0], ah[mi][1], ah[mi][2], ah[mi][3], aAh + ao);
                ldsm4(al[mi][0], al[mi][1], al[mi][2], al[mi][3], aAl + ao);
            }
#pragma unroll
            for (int np = 0; np < NF / 2; np++) {
                uint32_t bo = (uint32_t)((n0w + np * 16 + ((lane >> 4) << 3) +
                                          (lane & 7)) * 40 +
                                         kk + ((lane >> 3) & 1) * 8) * 2;
                ldsm4(bh[2 * np][0], bh[2 * np][1], bh[2 * np + 1][0],
                      bh[2 * np + 1][1], aBh + bo);
                ldsm4(bl[2 * np][0], bl[2 * np][1], bl[2 * np + 1][0],
                      bl[2 * np + 1][1], aBl + bo);
            }
#pragma unroll
            for (int mi = 0; mi < MF; mi++)
#pragma unroll
                for (int ni = 0; ni < NF; ni++) {
                    mma16816(acc[mi][ni], ah[mi], bh[ni]);
                    mma16816(acc[mi][ni], al[mi], bh[ni]);
                    mma16816(acc[mi][ni], ah[mi], bl[ni]);
                }
        }
    }

    // ---- epilogue: fragment-direct ----
#pragma unroll
    for (int ni = 0; ni < NF; ni++) {
        const int col = col0 + n0w + ni * 8 + (lane & 3) * 2;
        float2 e = make_float2(0.f, 0.f);
        if (EPI == 0 || EPI == 1) {
            e = *(const float2*)(aux + col);
        } else if (EPI == 2) {
            float2 m = *(const float2*)(aux + (size_t)zb * Ss + col);
            e.x = (1.f - m.x) * -10000.f;
            e.y = (1.f - m.y) * -10000.f;
        }
#pragma unroll
        for (int mi = 0; mi < MF; mi++) {
            const int r0g = row0 + m0w + mi * 16 + (lane >> 2);
            float* a = acc[mi][ni];
            float2 v0, v1;
            if (EPI == 2) {
                v0 = make_float2(a[0] * 0.125f + e.x, a[1] * 0.125f + e.y);
                v1 = make_float2(a[2] * 0.125f + e.x, a[3] * 0.125f + e.y);
            } else {
                v0 = make_float2(a[0] + e.x, a[1] + e.y);
                v1 = make_float2(a[2] + e.x, a[3] + e.y);
                if (EPI == 1) {
                    v0.x = fmaxf(v0.x, 0.f); v0.y = fmaxf(v0.y, 0.f);
                    v1.x = fmaxf(v1.x, 0.f); v1.y = fmaxf(v1.y, 0.f);
                }
            }
            if (CFMT == 0) {
                *(float2*)(Cb + (size_t)r0g * ldc + col) = v0;
                *(float2*)(Cb + (size_t)(r0g + 8) * ldc + col) = v1;
            } else {
                store_pair(CbH, CbL, (size_t)r0g * ldc + col, v0);
                store_pair(CbH, CbL, (size_t)(r0g + 8) * ldc + col, v1);
            }
        }
    }
}

// ---------------------------------------------------------------------------
// Split fp32 tensor into fp16 hi/lo planes
// ---------------------------------------------------------------------------
__global__ void __launch_bounds__(256) split_f32(
    const float* __restrict__ X, __half* __restrict__ H, __half* __restrict__ L)
{
    size_t i = (size_t)blockIdx.x * 256 + threadIdx.x;
    float4 v = ((const float4*)X)[i];
    store_pair(H, L, i * 4,     make_float2(v.x, v.y));
    store_pair(H, L, i * 4 + 2, make_float2(v.z, v.w));
}

// Weight transpose + split: T[c][r] = split(W[r][c])
__global__ void transpose_split(const float* __restrict__ W,
                                __half* __restrict__ TH, __half* __restrict__ TL,
                                int R, int C)
{
    __shared__ float t[32][33];
    int c0 = blockIdx.x * 32, r0 = blockIdx.y * 32;
#pragma unroll
    for (int i = threadIdx.y; i < 32; i += 8)
        t[i][threadIdx.x] = W[(size_t)(r0 + i) * C + c0 + threadIdx.x];
    __syncthreads();
#pragma unroll
    for (int i = threadIdx.y; i < 32; i += 8) {
        float v = t[threadIdx.x][i];
        __half h = __float2half_rn(v);
        size_t o = (size_t)(c0 + i) * R + r0 + threadIdx.x;
        TH[o] = h;
        TL[o] = __float2half_rn(v - __half2float(h));
    }
}

// V^T per (b,h) on pairs: Vt[bh][d][sk] = V[b][sk][h*64+d]
__global__ void vt_pairs(const __half* __restrict__ VH, const __half* __restrict__ VL,
                         __half* __restrict__ TH, __half* __restrict__ TL)
{
    __shared__ __half t[2][32][33];
    const int bh = blockIdx.z, b = bh >> 4, h = bh & 15;
    const int sk0 = blockIdx.x * 32, d0 = blockIdx.y * 32;
    const __half* vh = VH + (size_t)b * Ss * Dd + h * HDIM;
    const __half* vl = VL + (size_t)b * Ss * Dd + h * HDIM;
#pragma unroll
    for (int i = threadIdx.y; i < 32; i += 8) {
        t[0][i][threadIdx.x] = vh[(size_t)(sk0 + i) * Dd + d0 + threadIdx.x];
        t[1][i][threadIdx.x] = vl[(size_t)(sk0 + i) * Dd + d0 + threadIdx.x];
    }
    __syncthreads();
    __half* oh = TH + (size_t)bh * HDIM * Ss;
    __half* ol = TL + (size_t)bh * HDIM * Ss;
#pragma unroll
    for (int i = threadIdx.y; i < 32; i += 8) {
        oh[(size_t)(d0 + i) * Ss + sk0 + threadIdx.x] = t[0][threadIdx.x][i];
        ol[(size_t)(d0 + i) * Ss + sk0 + threadIdx.x] = t[1][threadIdx.x][i];
    }
}

// ---------------------------------------------------------------------------
// Softmax over rows of 1024: P pairs out + optional fp32 mirror (attn_weights)
// ---------------------------------------------------------------------------
__global__ void __launch_bounds__(256) softmax_kernel(
    const float* __restrict__ S, float* __restrict__ ext,
    __half* __restrict__ PH, __half* __restrict__ PL)
{
    __shared__ float sbuf[8];
    const size_t row = blockIdx.x;
    const float* p = S + row * Ss;
    const int tid = threadIdx.x;
    const int lane = tid & 31, w = tid >> 5;

    float4 x = *(const float4*)(p + tid * 4);
    float m = fmaxf(fmaxf(x.x, x.y), fmaxf(x.z, x.w));
#pragma unroll
    for (int o = 16; o > 0; o >>= 1) m = fmaxf(m, __shfl_xor_sync(~0u, m, o));
    if (lane == 0) sbuf[w] = m;
    __syncthreads();
    m = sbuf[0];
#pragma unroll
    for (int i = 1; i < 8; i++) m = fmaxf(m, sbuf[i]);

    float4 e;
    e.x = expf(x.x - m); e.y = expf(x.y - m);
    e.z = expf(x.z - m); e.w = expf(x.w - m);
    float s = e.x + e.y + e.z + e.w;
#pragma unroll
    for (int o = 16; o > 0; o >>= 1) s += __shfl_xor_sync(~0u, s, o);
    __syncthreads();
    if (lane == 0) sbuf[w] = s;
    __syncthreads();
    s = 0.f;
#pragma unroll
    for (int i = 0; i < 8; i++) s += sbuf[i];
    float inv = 1.0f / s;
    e.x *= inv; e.y *= inv; e.z *= inv; e.w *= inv;
    if (ext) *(float4*)(ext + row * Ss + tid * 4) = e;
    store_pair(PH, PL, row * Ss + tid * 4,     make_float2(e.x, e.y));
    store_pair(PH, PL, row * Ss + tid * 4 + 2, make_float2(e.z, e.w));
}

// ---------------------------------------------------------------------------
// LayerNorm kernels
// ---------------------------------------------------------------------------
__device__ __forceinline__ float block_sum(float v, float* sbuf) {
    const int lane = threadIdx.x & 31, w = threadIdx.x >> 5;
#pragma unroll
    for (int o = 16; o > 0; o >>= 1) v += __shfl_xor_sync(~0u, v, o);
    __syncthreads();
    if (lane == 0) sbuf[w] = v;
    __syncthreads();
    float s = 0.f;
#pragma unroll
    for (int i = 0; i < 8; i++) s += sbuf[i];
    return s;
}

// t = X + q ; ln1 = LN(t,1e-8) ; t2 = q + ln1 ; out = LN(t2,1e-6)
// Writes fp32 attn_out (residual for ln_b) AND fp16 pairs (FFN1 operand).
__global__ void __launch_bounds__(256) ln_a_kernel(
    const float* __restrict__ X, const float* __restrict__ q,
    const float* __restrict__ g1, const float* __restrict__ b1,
    const float* __restrict__ g2, const float* __restrict__ b2,
    float* __restrict__ out, __half* __restrict__ OH, __half* __restrict__ OL)
{
    __shared__ float sbuf[8];
    const size_t row = blockIdx.x;
    const int col = threadIdx.x * 4;
    float4 xv = *(const float4*)(X + row * Dd + col);
    float4 qv = *(const float4*)(q + row * Dd + col);
    float t[4] = { xv.x + qv.x, xv.y + qv.y, xv.z + qv.z, xv.w + qv.w };

    float mu = block_sum(t[0] + t[1] + t[2] + t[3], sbuf) * (1.0f / Dd);
    float ss = 0.f;
#pragma unroll
    for (int i = 0; i < 4; i++) { float d = t[i] - mu; ss += d * d; }
    float var = block_sum(ss, sbuf) * (1.0f / Dd);
    float inv = rsqrtf(var + 1e-8f);

    float4 g = *(const float4*)(g1 + col);
    float4 be = *(const float4*)(b1 + col);
    float qarr[4] = { qv.x, qv.y, qv.z, qv.w };
    float garr[4] = { g.x, g.y, g.z, g.w };
    float barr[4] = { be.x, be.y, be.z, be.w };
    float t2[4];
#pragma unroll
    for (int i = 0; i < 4; i++)
        t2[i] = qarr[i] + (t[i] - mu) * inv * garr[i] + barr[i];

    float mu2 = block_sum(t2[0] + t2[1] + t2[2] + t2[3], sbuf) * (1.0f / Dd);
    float ss2 = 0.f;
#pragma unroll
    for (int i = 0; i < 4; i++) { float d = t2[i] - mu2; ss2 += d * d; }
    float var2 = block_sum(ss2, sbuf) * (1.0f / Dd);
    float inv2 = rsqrtf(var2 + 1e-6f);

    g = *(const float4*)(g2 + col);
    be = *(const float4*)(b2 + col);
    float4 o;
    o.x = (t2[0] - mu2) * inv2 * g.x + be.x;
    o.y = (t2[1] - mu2) * inv2 * g.y + be.y;
    o.z = (t2[2] - mu2) * inv2 * g.z + be.z;
    o.w = (t2[3] - mu2) * inv2 * g.w + be.w;
    *(float4*)(out + row * Dd + col) = o;
    store_pair(OH, OL, row * Dd + col,     make_float2(o.x, o.y));
    store_pair(OH, OL, row * Dd + col + 2, make_float2(o.z, o.w));
}

__global__ void __launch_bounds__(256) ln_b_kernel(
    const float* __restrict__ Z, const float* __restrict__ res,
    const float* __restrict__ g1, const float* __restrict__ b1,
    float* __restrict__ out)
{
    __shared__ float sbuf[8];
    const size_t row = blockIdx.x;
    const int col = threadIdx.x * 4;
    float4 zv = *(const float4*)(Z + row * Dd + col);
    float4 rv = *(const float4*)(res + row * Dd + col);
    float t[4] = { zv.x + rv.x, zv.y + rv.y, zv.z + rv.z, zv.w + rv.w };

    float mu = block_sum(t[0] + t[1] + t[2] + t[3], sbuf) * (1.0f / Dd);
    float ss = 0.f;
#pragma unroll
    for (int i = 0; i < 4; i++) { float d = t[i] - mu; ss += d * d; }
    float var = block_sum(ss, sbuf) * (1.0f / Dd);
    float inv = rsqrtf(var + 1e-6f);

    float4 g = *(const float4*)(g1 + col);
    float4 be = *(const float4*)(b1 + col);
    float4 o;
    o.x = (t[0] - mu) * inv * g.x + be.x;
    o.y = (t[1] - mu) * inv * g.y + be.y;
    o.z = (t[2] - mu) * inv * g.z + be.z;
    o.w = (t[3] - mu) * inv * g.w + be.w;
    *(float4*)(out + row * Dd + col) = o;
}

// ---------------------------------------------------------------------------
// kernel_launch
// ---------------------------------------------------------------------------
extern "C" void kernel_launch(void* const* d_in, const int* in_sizes, int n_in,
                              void* d_out, int out_size)
{
    const float* query = (const float*)d_in[0];
    const float* key   = (const float*)d_in[1];
    const float* value = (const float*)d_in[2];
    const float* mask  = (const float*)d_in[3];
    const float* wq = (const float*)d_in[4];
    const float* bq = (const float*)d_in[5];
    const float* wk = (const float*)d_in[6];
    const float* bk = (const float*)d_in[7];
    const float* wv = (const float*)d_in[8];
    const float* bv = (const float*)d_in[9];
    const float* wo = (const float*)d_in[10];
    const float* bo = (const float*)d_in[11];
    const float* ln_mha_g = (const float*)d_in[12];
    const float* ln_mha_b = (const float*)d_in[13];
    const float* w1 = (const float*)d_in[14];
    const float* b1 = (const float*)d_in[15];
    const float* w2 = (const float*)d_in[16];
    const float* b2 = (const float*)d_in[17];
    const float* ln_attn_g = (const float*)d_in[18];
    const float* ln_attn_b = (const float*)d_in[19];
    const float* ln_ffn_g = (const float*)d_in[20];
    const float* ln_ffn_b = (const float*)d_in[21];
    (void)in_sizes; (void)n_in;

    float* out = (float*)d_out;

    __half *qp, *kp, *vp, *Qp, *Kp, *Vp, *Vtp, *ctx, *aop, *Fp, *Pp, *WTp;
    float *S, *X, *ao, *Z;
    cudaGetSymbolAddress((void**)&qp, g_qp);
    cudaGetSymbolAddress((void**)&kp, g_kp);
    cudaGetSymbolAddress((void**)&vp, g_vp);
    cudaGetSymbolAddress((void**)&Qp, g_Qp);
    cudaGetSymbolAddress((void**)&Kp, g_Kp);
    cudaGetSymbolAddress((void**)&Vp, g_Vp);
    cudaGetSymbolAddress((void**)&Vtp, g_Vtp);
    cudaGetSymbolAddress((void**)&ctx, g_ctx);
    cudaGetSymbolAddress((void**)&aop, g_aop);
    cudaGetSymbolAddress((void**)&Fp, g_Fp);
    cudaGetSymbolAddress((void**)&Pp, g_Pp);
    cudaGetSymbolAddress((void**)&WTp, g_WTp);
    cudaGetSymbolAddress((void**)&S, g_S);
    cudaGetSymbolAddress((void**)&X, g_X);
    cudaGetSymbolAddress((void**)&ao, g_ao);
    cudaGetSymbolAddress((void**)&Z, g_Z);

    const size_t nMD = (size_t)Mm * Dd;          // 8M
    const size_t nMF = (size_t)Mm * Ff;          // 32M
    const size_t nS  = (size_t)Bb * Hh * Ss * Ss;// 128M
    const size_t nVt = (size_t)Bb * Hh * HDIM * Ss;

    // plane pointers (lo = hi + n)
    __half *qpH = qp, *qpL = qp + nMD;
    __half *kpH = kp, *kpL = kp + nMD;
    __half *vpH = vp, *vpL = vp + nMD;
    __half *QpH = Qp, *QpL = Qp + nMD;
    __half *KpH = Kp, *KpL = Kp + nMD;
    __half *VpH = Vp, *VpL = Vp + nMD;
    __half *VtH = Vtp, *VtL = Vtp + nVt;
    __half *cxH = ctx, *cxL = ctx + nMD;
    __half *aoH = aop, *aoL = aop + nMD;
    __half *FpH = Fp, *FpL = Fp + nMF;
    __half *PpH = Pp, *PpL = Pp + nS;

    const size_t wsz = (size_t)4 * Dd * Dd + (size_t)Dd * Ff + (size_t)Ff * Dd;
    __half* WTh = WTp;          __half* WTl = WTp + wsz;
    __half *wqTH = WTh,                      *wqTL = WTl;
    __half *wkTH = WTh + (size_t)Dd * Dd,    *wkTL = WTl + (size_t)Dd * Dd;
    __half *wvTH = WTh + (size_t)2 * Dd * Dd,*wvTL = WTl + (size_t)2 * Dd * Dd;
    __half *woTH = WTh + (size_t)3 * Dd * Dd,*woTL = WTl + (size_t)3 * Dd * Dd;
    __half *w1TH = WTh + (size_t)4 * Dd * Dd,*w1TL = WTl + (size_t)4 * Dd * Dd;
    __half *w2TH = w1TH + (size_t)Dd * Ff,   *w2TL = w1TL + (size_t)Dd * Ff;

    const long long main_elems = (long long)Mm * Dd;
    const long long attn_elems = (long long)nS;
    float* attn_ext = ((long long)out_size >= main_elems + attn_elems)
                          ? (out + main_elems) : nullptr;

    const int DSZ128 = 3 * (20480 + 128 * 160);   // 122880
    const int DSZ64  = 3 * (20480 + 64 * 160);    // 92160
    cudaFuncSetAttribute(gemm_ps<128,0,1>, cudaFuncAttributeMaxDynamicSharedMemorySize, DSZ128);
    cudaFuncSetAttribute(gemm_ps<128,0,0>, cudaFuncAttributeMaxDynamicSharedMemorySize, DSZ128);
    cudaFuncSetAttribute(gemm_ps<128,1,1>, cudaFuncAttributeMaxDynamicSharedMemorySize, DSZ128);
    cudaFuncSetAttribute(gemm_ps<128,2,0>, cudaFuncAttributeMaxDynamicSharedMemorySize, DSZ128);
    cudaFuncSetAttribute(gemm_ps<64,3,1>,  cudaFuncAttributeMaxDynamicSharedMemorySize, DSZ64);

    dim3 tblk(32, 8);

    // Input splits + weight transpose-splits
    split_f32<<<nMD / 1024, 256>>>(query, qpH, qpL);
    split_f32<<<nMD / 1024, 256>>>(key,   kpH, kpL);
    split_f32<<<nMD / 1024, 256>>>(value, vpH, vpL);
    transpose_split<<<dim3(Dd/32, Dd/32), tblk>>>(wq, wqTH, wqTL, Dd, Dd);
    transpose_split<<<dim3(Dd/32, Dd/32), tblk>>>(wk, wkTH, wkTL, Dd, Dd);
    transpose_split<<<dim3(Dd/32, Dd/32), tblk>>>(wv, wvTH, wvTL, Dd, Dd);
    transpose_split<<<dim3(Dd/32, Dd/32), tblk>>>(wo, woTH, woTL, Dd, Dd);
    transpose_split<<<dim3(Ff/32, Dd/32), tblk>>>(w1, w1TH, w1TL, Dd, Ff);
    transpose_split<<<dim3(Dd/32, Ff/32), tblk>>>(w2, w2TH, w2TL, Ff, Dd);

    // QKV projections -> pairs
    gemm_ps<128,0,1><<<dim3(Dd/128, Mm/128, 1), 256, DSZ128>>>(
        qpH, qpL, Dd, 0, 0, wqTH, wqTL, Dd, 0, 0,
        nullptr, QpH, QpL, Dd, 0, 0, bq, Dd);
    gemm_ps<128,0,1><<<dim3(Dd/128, Mm/128, 1), 256, DSZ128>>>(
        kpH, kpL, Dd, 0, 0, wkTH, wkTL, Dd, 0, 0,
        nullptr, KpH, KpL, Dd, 0, 0, bk, Dd);
    gemm_ps<128,0,1><<<dim3(Dd/128, Mm/128, 1), 256, DSZ128>>>(
        vpH, vpL, Dd, 0, 0, wvTH, wvTL, Dd, 0, 0,
        nullptr, VpH, VpL, Dd, 0, 0, bv, Dd);

    // V^T per head (pairs)
    vt_pairs<<<dim3(Ss/32, HDIM/32, Bb*Hh), tblk>>>(VpH, VpL, VtH, VtL);

    // scores = QK^T/8 + mask -> fp32 S
    gemm_ps<128,2,0><<<dim3(Ss/128, Ss/128, Bb*Hh), 256, DSZ128>>>(
        QpH, QpL, Dd, (long long)Ss*Dd, HDIM,
        KpH, KpL, Dd, (long long)Ss*Dd, HDIM,
        S, nullptr, nullptr, Ss, 16LL*Ss*Ss, (long long)Ss*Ss,
        mask, HDIM);

    // softmax -> P pairs (+ attn_weights mirror)
    softmax_kernel<<<Bb*Hh*Ss, 256>>>(S, attn_ext, PpH, PpL);

    // context = P @ V -> pairs
    gemm_ps<64,3,1><<<dim3(1, Ss/128, Bb*Hh), 256, DSZ64>>>(
        PpH, PpL, Ss, 16LL*Ss*Ss, (long long)Ss*Ss,
        VtH, VtL, Ss, 16LL*HDIM*Ss, (long long)HDIM*Ss,
        nullptr, cxH, cxL, Dd, (long long)Ss*Dd, HDIM,
        nullptr, Ss);

    // O-projection -> fp32 X
    gemm_ps<128,0,0><<<dim3(Dd/128, Mm/128, 1), 256, DSZ128>>>(
        cxH, cxL, Dd, 0, 0, woTH, woTL, Dd, 0, 0,
        X, nullptr, nullptr, Dd, 0, 0, bo, Dd);

    // Double LayerNorm -> attn_out fp32 + pairs
    ln_a_kernel<<<Mm, 256>>>(X, query, ln_mha_g, ln_mha_b,
                             ln_attn_g, ln_attn_b, ao, aoH, aoL);

    // FFN1 -> F pairs (relu)
    gemm_ps<128,1,1><<<dim3(Ff/128, Mm/128, 1), 256, DSZ128>>>(
        aoH, aoL, Dd, 0, 0, w1TH, w1TL, Dd, 0, 0,
        nullptr, FpH, FpL, Ff, 0, 0, b1, Dd);

    // FFN2 -> fp32 Z
    gemm_ps<128,0,0><<<dim3(Dd/128, Mm/128, 1), 256, DSZ128>>>(
        FpH, FpL, Ff, 0, 0, w2TH, w2TL, Ff, 0, 0,
        Z, nullptr, nullptr, Dd, 0, 0, b2, Ff);

    // Final LayerNorm -> main output
    ln_b_kernel<<<Mm, 256>>>(Z, ao, ln_ffn_g, ln_ffn_b, out);
}

// round 5
// speedup vs baseline: 1.1785x; 1.1785x over previous
#include <cuda_runtime.h>
#include <cuda_fp16.h>
#include <math.h>
#include <stdint.h>

#define Bb 8
#define Ss 1024
#define Dd 1024
#define Hh 16
#define HDIM 64
#define Ff 4096
#define Mm (Bb*Ss)

// ---------------------------------------------------------------------------
// Scratch (device globals). Pair tensors: [0..n) = hi plane, [n..2n) = lo.
// ---------------------------------------------------------------------------
__device__ __half g_qp [2*(size_t)Mm*Dd];
__device__ __half g_kp [2*(size_t)Mm*Dd];
__device__ __half g_vp [2*(size_t)Mm*Dd];
__device__ __half g_Qp [2*(size_t)Mm*Dd];
__device__ __half g_Kp [2*(size_t)Mm*Dd];
__device__ __half g_Vp [2*(size_t)Mm*Dd];
__device__ __half g_Vtp[2*(size_t)Bb*Hh*HDIM*Ss];
__device__ __half g_ctx[2*(size_t)Mm*Dd];
__device__ __half g_aop[2*(size_t)Mm*Dd];
__device__ __half g_Fp [2*(size_t)Mm*Ff];
__device__ __half g_Ph [(size_t)Bb*Hh*Ss*Ss];      // P: single fp16 plane
__device__ __half g_WTp[2*(size_t)(4*Dd*Dd + Dd*Ff + Ff*Dd)];
__device__ float  g_S  [(size_t)Bb*Hh*Ss*Ss];
__device__ float  g_X  [(size_t)Mm*Dd];
__device__ float  g_ao [(size_t)Mm*Dd];
__device__ float  g_Z  [(size_t)Mm*Dd];

// ---------------------------------------------------------------------------
// PTX helpers (baseline sm_80+ features, valid on plain sm_103 target)
// ---------------------------------------------------------------------------
__device__ __forceinline__ uint32_t smem_u32(const void* p) {
    uint32_t a;
    asm("{ .reg .u64 t; cvta.to.shared.u64 t, %1; cvt.u32.u64 %0, t; }"
        : "=r"(a) : "l"(p));
    return a;
}
__device__ __forceinline__ void ldsm4(uint32_t& r0, uint32_t& r1, uint32_t& r2,
                                      uint32_t& r3, uint32_t addr) {
    asm volatile("ldmatrix.sync.aligned.m8n8.x4.shared.b16 {%0,%1,%2,%3}, [%4];"
                 : "=r"(r0), "=r"(r1), "=r"(r2), "=r"(r3) : "r"(addr));
}
__device__ __forceinline__ void mma16816(float* d, const uint32_t* a,
                                         const uint32_t* b) {
    asm volatile(
        "mma.sync.aligned.m16n8k16.row.col.f32.f16.f16.f32 "
        "{%0,%1,%2,%3}, {%4,%5,%6,%7}, {%8,%9}, {%0,%1,%2,%3};"
        : "+f"(d[0]), "+f"(d[1]), "+f"(d[2]), "+f"(d[3])
        : "r"(a[0]), "r"(a[1]), "r"(a[2]), "r"(a[3]), "r"(b[0]), "r"(b[1]));
}
__device__ __forceinline__ void cpa16(uint32_t dst, const void* src) {
    asm volatile("cp.async.cg.shared.global [%0], [%1], 16;"
                 :: "r"(dst), "l"(src) : "memory");
}
#define CP_COMMIT() asm volatile("cp.async.commit_group;" ::: "memory")
#define CP_WAIT0()  asm volatile("cp.async.wait_group 0;" ::: "memory")

// fp32 pair split store: hi = f16(x), lo = f16(x - hi)
__device__ __forceinline__ void store_pair(__half* H, __half* L, size_t off,
                                           float2 v) {
    __half2 h = __floats2half2_rn(v.x, v.y);
    float2 hf = __half22float2(h);
    __half2 l = __floats2half2_rn(v.x - hf.x, v.y - hf.y);
    *(__half2*)(H + off) = h;
    *(__half2*)(L + off) = l;
}

// ---------------------------------------------------------------------------
// GEMM on fp16 operands via mma.sync, fp32-equivalent accuracy:
//   C[128 x BN] = A[128,K] @ B[BN,K]^T, fp32 accum.
//   AFMT=0: A is hi/lo pair -> D = Ah*Bh + Al*Bh + Ah*Bl  (3 MMAs)
//   AFMT=2: A is single fp16 -> D = A*Bh + A*Bl           (2 MMAs)
//   B always hi/lo pair. 2-stage cp.async pipeline, 2 CTAs/SM.
//   Batch via blockIdx.z: off = (z>>4)*s1 + (z&15)*s2 (elements per plane).
//   EPI: 0=+bias  1=+bias,relu  2=scores(x/8+(1-mask)*-1e4)  3=plain
//   CFMT: 0 = fp32 out (C) ; 1 = fp16 pair out (CH/CL)
// ---------------------------------------------------------------------------
template<int BN, int EPI, int CFMT, int AFMT>
__global__ void __launch_bounds__(256, 2) gemm_ps(
    const __half* __restrict__ AH, const __half* __restrict__ AL,
    long long lda, long long a1, long long a2,
    const __half* __restrict__ BH, const __half* __restrict__ BL,
    long long ldb, long long b1, long long b2,
    float* __restrict__ C, __half* __restrict__ CH, __half* __restrict__ CL,
    long long ldc, long long c1, long long c2,
    const float* __restrict__ aux, int K)
{
    constexpr int MF = 4;                 // m16 frags per warp (m span 64)
    constexpr int NF = BN / 32;           // n8 frags per warp (n span BN/4)
    constexpr int NBI = BN / 64;          // B cp.async iters per plane
    constexpr int ABYTES = (AFMT == 0) ? 20480 : 10240;
    constexpr int STAGE = ABYTES + BN * 160;

    extern __shared__ char dsm[];

    const int tid = threadIdx.x, lane = tid & 31, wid = tid >> 5;
    const int zb = blockIdx.z >> 4, zh = blockIdx.z & 15;
    const int row0 = blockIdx.y * 128, col0 = blockIdx.x * BN;
    const int m0w = (wid >> 2) * 64, n0w = (wid & 3) * (BN / 4);

    const __half* Abh = AH + zb * a1 + zh * a2 + (size_t)row0 * lda;
    const __half* Abl = (AFMT == 0) ? (AL + zb * a1 + zh * a2 + (size_t)row0 * lda)
                                    : nullptr;
    const __half* Bbh = BH + zb * b1 + zh * b2 + (size_t)col0 * ldb;
    const __half* Bbl = BL + zb * b1 + zh * b2 + (size_t)col0 * ldb;
    float* Cb = C + zb * c1 + zh * c2;
    __half* CbH = CH + zb * c1 + zh * c2;
    __half* CbL = CL + zb * c1 + zh * c2;

    const uint32_t sbase = smem_u32(dsm);

    float acc[MF][NF][4];
#pragma unroll
    for (int i = 0; i < MF; i++)
#pragma unroll
        for (int j = 0; j < NF; j++)
#pragma unroll
            for (int k = 0; k < 4; k++) acc[i][j][k] = 0.f;

    auto issue = [&](int st, int k0) {
        uint32_t base = sbase + st * STAGE;
#pragma unroll
        for (int i = 0; i < 2; i++) {       // A: 128 rows x 4 16B groups
            int q = tid + i * 256;
            int r = q >> 2, g = q & 3;
            uint32_t d = base + r * 80 + g * 16;
            cpa16(d, Abh + (size_t)r * lda + k0 + g * 8);
            if (AFMT == 0)
                cpa16(d + 10240, Abl + (size_t)r * lda + k0 + g * 8);
        }
#pragma unroll
        for (int i = 0; i < NBI; i++) {     // B: BN rows x 4 groups, 2 planes
            int q = tid + i * 256;
            int r = q >> 2, g = q & 3;
            uint32_t d = base + ABYTES + r * 80 + g * 16;
            cpa16(d,           Bbh + (size_t)r * ldb + k0 + g * 8);
            cpa16(d + BN * 80, Bbl + (size_t)r * ldb + k0 + g * 8);
        }
        CP_COMMIT();
    };

    const int NC = K >> 5;
    issue(0, 0);

    for (int c = 0; c < NC; c++) {
        CP_WAIT0();
        __syncthreads();
        if (c + 1 < NC) issue((c + 1) & 1, (c + 1) * 32);

        const uint32_t aAh = sbase + (c & 1) * STAGE;
        const uint32_t aAl = aAh + 10240;
        const uint32_t aBh = aAh + ABYTES;
        const uint32_t aBl = aBh + BN * 80;
#pragma unroll
        for (int kk = 0; kk < 32; kk += 16) {
            uint32_t bh[NF][2], bl[NF][2];
#pragma unroll
            for (int np = 0; np < NF / 2; np++) {
                uint32_t bo = (uint32_t)((n0w + np * 16 + ((lane >> 4) << 3) +
                                          (lane & 7)) * 40 +
                                         kk + ((lane >> 3) & 1) * 8) * 2;
                ldsm4(bh[2 * np][0], bh[2 * np][1], bh[2 * np + 1][0],
                      bh[2 * np + 1][1], aBh + bo);
                ldsm4(bl[2 * np][0], bl[2 * np][1], bl[2 * np + 1][0],
                      bl[2 * np + 1][1], aBl + bo);
            }
#pragma unroll
            for (int mi = 0; mi < MF; mi++) {
                uint32_t ao = (uint32_t)((m0w + mi * 16 + (lane & 15)) * 40 +
                                         kk + ((lane >> 4) << 3)) * 2;
                uint32_t ah[4];
                ldsm4(ah[0], ah[1], ah[2], ah[3], aAh + ao);
                if (AFMT == 0) {
                    uint32_t al[4];
                    ldsm4(al[0], al[1], al[2], al[3], aAl + ao);
#pragma unroll
                    for (int ni = 0; ni < NF; ni++) {
                        mma16816(acc[mi][ni], ah, bh[ni]);
                        mma16816(acc[mi][ni], al, bh[ni]);
                        mma16816(acc[mi][ni], ah, bl[ni]);
                    }
                } else {
#pragma unroll
                    for (int ni = 0; ni < NF; ni++) {
                        mma16816(acc[mi][ni], ah, bh[ni]);
                        mma16816(acc[mi][ni], ah, bl[ni]);
                    }
                }
            }
        }
        __syncthreads();
    }

    // ---- epilogue: fragment-direct ----
#pragma unroll
    for (int ni = 0; ni < NF; ni++) {
        const int col = col0 + n0w + ni * 8 + (lane & 3) * 2;
        float2 e = make_float2(0.f, 0.f);
        if (EPI == 0 || EPI == 1) {
            e = *(const float2*)(aux + col);
        } else if (EPI == 2) {
            float2 m = *(const float2*)(aux + (size_t)zb * Ss + col);
            e.x = (1.f - m.x) * -10000.f;
            e.y = (1.f - m.y) * -10000.f;
        }
#pragma unroll
        for (int mi = 0; mi < MF; mi++) {
            const int r0g = row0 + m0w + mi * 16 + (lane >> 2);
            float* a = acc[mi][ni];
            float2 v0, v1;
            if (EPI == 2) {
                v0 = make_float2(a[0] * 0.125f + e.x, a[1] * 0.125f + e.y);
                v1 = make_float2(a[2] * 0.125f + e.x, a[3] * 0.125f + e.y);
            } else {
                v0 = make_float2(a[0] + e.x, a[1] + e.y);
                v1 = make_float2(a[2] + e.x, a[3] + e.y);
                if (EPI == 1) {
                    v0.x = fmaxf(v0.x, 0.f); v0.y = fmaxf(v0.y, 0.f);
                    v1.x = fmaxf(v1.x, 0.f); v1.y = fmaxf(v1.y, 0.f);
                }
            }
            if (CFMT == 0) {
                *(float2*)(Cb + (size_t)r0g * ldc + col) = v0;
                *(float2*)(Cb + (size_t)(r0g + 8) * ldc + col) = v1;
            } else {
                store_pair(CbH, CbL, (size_t)r0g * ldc + col, v0);
                store_pair(CbH, CbL, (size_t)(r0g + 8) * ldc + col, v1);
            }
        }
    }
}

// ---------------------------------------------------------------------------
// Split fp32 tensor into fp16 hi/lo planes
// ---------------------------------------------------------------------------
__global__ void __launch_bounds__(256) split_f32(
    const float* __restrict__ X, __half* __restrict__ H, __half* __restrict__ L)
{
    size_t i = (size_t)blockIdx.x * 256 + threadIdx.x;
    float4 v = ((const float4*)X)[i];
    store_pair(H, L, i * 4,     make_float2(v.x, v.y));
    store_pair(H, L, i * 4 + 2, make_float2(v.z, v.w));
}

// Weight transpose + split: T[c][r] = split(W[r][c])
__global__ void transpose_split(const float* __restrict__ W,
                                __half* __restrict__ TH, __half* __restrict__ TL,
                                int R, int C)
{
    __shared__ float t[32][33];
    int c0 = blockIdx.x * 32, r0 = blockIdx.y * 32;
#pragma unroll
    for (int i = threadIdx.y; i < 32; i += 8)
        t[i][threadIdx.x] = W[(size_t)(r0 + i) * C + c0 + threadIdx.x];
    __syncthreads();
#pragma unroll
    for (int i = threadIdx.y; i < 32; i += 8) {
        float v = t[threadIdx.x][i];
        __half h = __float2half_rn(v);
        size_t o = (size_t)(c0 + i) * R + r0 + threadIdx.x;
        TH[o] = h;
        TL[o] = __float2half_rn(v - __half2float(h));
    }
}

// V^T per (b,h) on pairs: Vt[bh][d][sk] = V[b][sk][h*64+d]
__global__ void vt_pairs(const __half* __restrict__ VH, const __half* __restrict__ VL,
                         __half* __restrict__ TH, __half* __restrict__ TL)
{
    __shared__ __half t[2][32][33];
    const int bh = blockIdx.z, b = bh >> 4, h = bh & 15;
    const int sk0 = blockIdx.x * 32, d0 = blockIdx.y * 32;
    const __half* vh = VH + (size_t)b * Ss * Dd + h * HDIM;
    const __half* vl = VL + (size_t)b * Ss * Dd + h * HDIM;
#pragma unroll
    for (int i = threadIdx.y; i < 32; i += 8) {
        t[0][i][threadIdx.x] = vh[(size_t)(sk0 + i) * Dd + d0 + threadIdx.x];
        t[1][i][threadIdx.x] = vl[(size_t)(sk0 + i) * Dd + d0 + threadIdx.x];
    }
    __syncthreads();
    __half* oh = TH + (size_t)bh * HDIM * Ss;
    __half* ol = TL + (size_t)bh * HDIM * Ss;
#pragma unroll
    for (int i = threadIdx.y; i < 32; i += 8) {
        oh[(size_t)(d0 + i) * Ss + sk0 + threadIdx.x] = t[0][threadIdx.x][i];
        ol[(size_t)(d0 + i) * Ss + sk0 + threadIdx.x] = t[1][threadIdx.x][i];
    }
}

// ---------------------------------------------------------------------------
// Softmax over rows of 1024: fp32 mirror (attn_weights) + single fp16 P plane
// ---------------------------------------------------------------------------
__global__ void __launch_bounds__(256) softmax_kernel(
    const float* __restrict__ S, float* __restrict__ ext,
    __half* __restrict__ PH)
{
    __shared__ float sbuf[8];
    const size_t row = blockIdx.x;
    const float* p = S + row * Ss;
    const int tid = threadIdx.x;
    const int lane = tid & 31, w = tid >> 5;

    float4 x = *(const float4*)(p + tid * 4);
    float m = fmaxf(fmaxf(x.x, x.y), fmaxf(x.z, x.w));
#pragma unroll
    for (int o = 16; o > 0; o >>= 1) m = fmaxf(m, __shfl_xor_sync(~0u, m, o));
    if (lane == 0) sbuf[w] = m;
    __syncthreads();
    m = sbuf[0];
#pragma unroll
    for (int i = 1; i < 8; i++) m = fmaxf(m, sbuf[i]);

    float4 e;
    e.x = expf(x.x - m); e.y = expf(x.y - m);
    e.z = expf(x.z - m); e.w = expf(x.w - m);
    float s = e.x + e.y + e.z + e.w;
#pragma unroll
    for (int o = 16; o > 0; o >>= 1) s += __shfl_xor_sync(~0u, s, o);
    __syncthreads();
    if (lane == 0) sbuf[w] = s;
    __syncthreads();
    s = 0.f;
#pragma unroll
    for (int i = 0; i < 8; i++) s += sbuf[i];
    float inv = 1.0f / s;
    e.x *= inv; e.y *= inv; e.z *= inv; e.w *= inv;
    if (ext) *(float4*)(ext + row * Ss + tid * 4) = e;
    __half2 p0 = __floats2half2_rn(e.x, e.y);
    __half2 p1 = __floats2half2_rn(e.z, e.w);
    *(__half2*)(PH + row * Ss + tid * 4)     = p0;
    *(__half2*)(PH + row * Ss + tid * 4 + 2) = p1;
}

// ---------------------------------------------------------------------------
// LayerNorm kernels
// ---------------------------------------------------------------------------
__device__ __forceinline__ float block_sum(float v, float* sbuf) {
    const int lane = threadIdx.x & 31, w = threadIdx.x >> 5;
#pragma unroll
    for (int o = 16; o > 0; o >>= 1) v += __shfl_xor_sync(~0u, v, o);
    __syncthreads();
    if (lane == 0) sbuf[w] = v;
    __syncthreads();
    float s = 0.f;
#pragma unroll
    for (int i = 0; i < 8; i++) s += sbuf[i];
    return s;
}

// t = X + q ; ln1 = LN(t,1e-8) ; t2 = q + ln1 ; out = LN(t2,1e-6)
__global__ void __launch_bounds__(256) ln_a_kernel(
    const float* __restrict__ X, const float* __restrict__ q,
    const float* __restrict__ g1, const float* __restrict__ b1,
    const float* __restrict__ g2, const float* __restrict__ b2,
    float* __restrict__ out, __half* __restrict__ OH, __half* __restrict__ OL)
{
    __shared__ float sbuf[8];
    const size_t row = blockIdx.x;
    const int col = threadIdx.x * 4;
    float4 xv = *(const float4*)(X + row * Dd + col);
    float4 qv = *(const float4*)(q + row * Dd + col);
    float t[4] = { xv.x + qv.x, xv.y + qv.y, xv.z + qv.z, xv.w + qv.w };

    float mu = block_sum(t[0] + t[1] + t[2] + t[3], sbuf) * (1.0f / Dd);
    float ss = 0.f;
#pragma unroll
    for (int i = 0; i < 4; i++) { float d = t[i] - mu; ss += d * d; }
    float var = block_sum(ss, sbuf) * (1.0f / Dd);
    float inv = rsqrtf(var + 1e-8f);

    float4 g = *(const float4*)(g1 + col);
    float4 be = *(const float4*)(b1 + col);
    float qarr[4] = { qv.x, qv.y, qv.z, qv.w };
    float garr[4] = { g.x, g.y, g.z, g.w };
    float barr[4] = { be.x, be.y, be.z, be.w };
    float t2[4];
#pragma unroll
    for (int i = 0; i < 4; i++)
        t2[i] = qarr[i] + (t[i] - mu) * inv * garr[i] + barr[i];

    float mu2 = block_sum(t2[0] + t2[1] + t2[2] + t2[3], sbuf) * (1.0f / Dd);
    float ss2 = 0.f;
#pragma unroll
    for (int i = 0; i < 4; i++) { float d = t2[i] - mu2; ss2 += d * d; }
    float var2 = block_sum(ss2, sbuf) * (1.0f / Dd);
    float inv2 = rsqrtf(var2 + 1e-6f);

    g = *(const float4*)(g2 + col);
    be = *(const float4*)(b2 + col);
    float4 o;
    o.x = (t2[0] - mu2) * inv2 * g.x + be.x;
    o.y = (t2[1] - mu2) * inv2 * g.y + be.y;
    o.z = (t2[2] - mu2) * inv2 * g.z + be.z;
    o.w = (t2[3] - mu2) * inv2 * g.w + be.w;
    *(float4*)(out + row * Dd + col) = o;
    store_pair(OH, OL, row * Dd + col,     make_float2(o.x, o.y));
    store_pair(OH, OL, row * Dd + col + 2, make_float2(o.z, o.w));
}

__global__ void __launch_bounds__(256) ln_b_kernel(
    const float* __restrict__ Z, const float* __restrict__ res,
    const float* __restrict__ g1, const float* __restrict__ b1,
    float* __restrict__ out)
{
    __shared__ float sbuf[8];
    const size_t row = blockIdx.x;
    const int col = threadIdx.x * 4;
    float4 zv = *(const float4*)(Z + row * Dd + col);
    float4 rv = *(const float4*)(res + row * Dd + col);
    float t[4] = { zv.x + rv.x, zv.y + rv.y, zv.z + rv.z, zv.w + rv.w };

    float mu = block_sum(t[0] + t[1] + t[2] + t[3], sbuf) * (1.0f / Dd);
    float ss = 0.f;
#pragma unroll
    for (int i = 0; i < 4; i++) { float d = t[i] - mu; ss += d * d; }
    float var = block_sum(ss, sbuf) * (1.0f / Dd);
    float inv = rsqrtf(var + 1e-6f);

    float4 g = *(const float4*)(g1 + col);
    float4 be = *(const float4*)(b1 + col);
    float4 o;
    o.x = (t[0] - mu) * inv * g.x + be.x;
    o.y = (t[1] - mu) * inv * g.y + be.y;
    o.z = (t[2] - mu) * inv * g.z + be.z;
    o.w = (t[3] - mu) * inv * g.w + be.w;
    *(float4*)(out + row * Dd + col) = o;
}

// ---------------------------------------------------------------------------
// kernel_launch
// ---------------------------------------------------------------------------
extern "C" void kernel_launch(void* const* d_in, const int* in_sizes, int n_in,
                              void* d_out, int out_size)
{
    const float* query = (const float*)d_in[0];
    const float* key   = (const float*)d_in[1];
    const float* value = (const float*)d_in[2];
    const float* mask  = (const float*)d_in[3];
    const float* wq = (const float*)d_in[4];
    const float* bq = (const float*)d_in[5];
    const float* wk = (const float*)d_in[6];
    const float* bk = (const float*)d_in[7];
    const float* wv = (const float*)d_in[8];
    const float* bv = (const float*)d_in[9];
    const float* wo = (const float*)d_in[10];
    const float* bo = (const float*)d_in[11];
    const float* ln_mha_g = (const float*)d_in[12];
    const float* ln_mha_b = (const float*)d_in[13];
    const float* w1 = (const float*)d_in[14];
    const float* b1 = (const float*)d_in[15];
    const float* w2 = (const float*)d_in[16];
    const float* b2 = (const float*)d_in[17];
    const float* ln_attn_g = (const float*)d_in[18];
    const float* ln_attn_b = (const float*)d_in[19];
    const float* ln_ffn_g = (const float*)d_in[20];
    const float* ln_ffn_b = (const float*)d_in[21];
    (void)in_sizes; (void)n_in;

    float* out = (float*)d_out;

    __half *qp, *kp, *vp, *Qp, *Kp, *Vp, *Vtp, *ctx, *aop, *Fp, *Ph, *WTp;
    float *S, *X, *ao, *Z;
    cudaGetSymbolAddress((void**)&qp, g_qp);
    cudaGetSymbolAddress((void**)&kp, g_kp);
    cudaGetSymbolAddress((void**)&vp, g_vp);
    cudaGetSymbolAddress((void**)&Qp, g_Qp);
    cudaGetSymbolAddress((void**)&Kp, g_Kp);
    cudaGetSymbolAddress((void**)&Vp, g_Vp);
    cudaGetSymbolAddress((void**)&Vtp, g_Vtp);
    cudaGetSymbolAddress((void**)&ctx, g_ctx);
    cudaGetSymbolAddress((void**)&aop, g_aop);
    cudaGetSymbolAddress((void**)&Fp, g_Fp);
    cudaGetSymbolAddress((void**)&Ph, g_Ph);
    cudaGetSymbolAddress((void**)&WTp, g_WTp);
    cudaGetSymbolAddress((void**)&S, g_S);
    cudaGetSymbolAddress((void**)&X, g_X);
    cudaGetSymbolAddress((void**)&ao, g_ao);
    cudaGetSymbolAddress((void**)&Z, g_Z);

    const size_t nMD = (size_t)Mm * Dd;
    const size_t nMF = (size_t)Mm * Ff;
    const size_t nS  = (size_t)Bb * Hh * Ss * Ss;
    const size_t nVt = (size_t)Bb * Hh * HDIM * Ss;

    __half *qpH = qp, *qpL = qp + nMD;
    __half *kpH = kp, *kpL = kp + nMD;
    __half *vpH = vp, *vpL = vp + nMD;
    __half *QpH = Qp, *QpL = Qp + nMD;
    __half *KpH = Kp, *KpL = Kp + nMD;
    __half *VpH = Vp, *VpL = Vp + nMD;
    __half *VtH = Vtp, *VtL = Vtp + nVt;
    __half *cxH = ctx, *cxL = ctx + nMD;
    __half *aoH = aop, *aoL = aop + nMD;
    __half *FpH = Fp, *FpL = Fp + nMF;

    const size_t wsz = (size_t)4 * Dd * Dd + (size_t)Dd * Ff + (size_t)Ff * Dd;
    __half* WTh = WTp;          __half* WTl = WTp + wsz;
    __half *wqTH = WTh,                      *wqTL = WTl;
    __half *wkTH = WTh + (size_t)Dd * Dd,    *wkTL = WTl + (size_t)Dd * Dd;
    __half *wvTH = WTh + (size_t)2 * Dd * Dd,*wvTL = WTl + (size_t)2 * Dd * Dd;
    __half *woTH = WTh + (size_t)3 * Dd * Dd,*woTL = WTl + (size_t)3 * Dd * Dd;
    __half *w1TH = WTh + (size_t)4 * Dd * Dd,*w1TL = WTl + (size_t)4 * Dd * Dd;
    __half *w2TH = w1TH + (size_t)Dd * Ff,   *w2TL = w1TL + (size_t)Dd * Ff;

    const long long main_elems = (long long)Mm * Dd;
    const long long attn_elems = (long long)nS;
    float* attn_ext = ((long long)out_size >= main_elems + attn_elems)
                          ? (out + main_elems) : nullptr;

    const int DSZ128 = 2 * (20480 + 128 * 160);   // 81920
    const int DSZ64A = 2 * (10240 + 64 * 160);    // 40960 (PV, AFMT=2)
    cudaFuncSetAttribute(gemm_ps<128,0,1,0>, cudaFuncAttributeMaxDynamicSharedMemorySize, DSZ128);
    cudaFuncSetAttribute(gemm_ps<128,0,0,0>, cudaFuncAttributeMaxDynamicSharedMemorySize, DSZ128);
    cudaFuncSetAttribute(gemm_ps<128,1,1,0>, cudaFuncAttributeMaxDynamicSharedMemorySize, DSZ128);
    cudaFuncSetAttribute(gemm_ps<128,2,0,0>, cudaFuncAttributeMaxDynamicSharedMemorySize, DSZ128);
    cudaFuncSetAttribute(gemm_ps<64,3,1,2>,  cudaFuncAttributeMaxDynamicSharedMemorySize, DSZ64A);

    dim3 tblk(32, 8);

    split_f32<<<nMD / 1024, 256>>>(query, qpH, qpL);
    split_f32<<<nMD / 1024, 256>>>(key,   kpH, kpL);
    split_f32<<<nMD / 1024, 256>>>(value, vpH, vpL);
    transpose_split<<<dim3(Dd/32, Dd/32), tblk>>>(wq, wqTH, wqTL, Dd, Dd);
    transpose_split<<<dim3(Dd/32, Dd/32), tblk>>>(wk, wkTH, wkTL, Dd, Dd);
    transpose_split<<<dim3(Dd/32, Dd/32), tblk>>>(wv, wvTH, wvTL, Dd, Dd);
    transpose_split<<<dim3(Dd/32, Dd/32), tblk>>>(wo, woTH, woTL, Dd, Dd);
    transpose_split<<<dim3(Ff/32, Dd/32), tblk>>>(w1, w1TH, w1TL, Dd, Ff);
    transpose_split<<<dim3(Dd/32, Ff/32), tblk>>>(w2, w2TH, w2TL, Ff, Dd);

    // QKV projections -> pairs
    gemm_ps<128,0,1,0><<<dim3(Dd/128, Mm/128, 1), 256, DSZ128>>>(
        qpH, qpL, Dd, 0, 0, wqTH, wqTL, Dd, 0, 0,
        nullptr, QpH, QpL, Dd, 0, 0, bq, Dd);
    gemm_ps<128,0,1,0><<<dim3(Dd/128, Mm/128, 1), 256, DSZ128>>>(
        kpH, kpL, Dd, 0, 0, wkTH, wkTL, Dd, 0, 0,
        nullptr, KpH, KpL, Dd, 0, 0, bk, Dd);
    gemm_ps<128,0,1,0><<<dim3(Dd/128, Mm/128, 1), 256, DSZ128>>>(
        vpH, vpL, Dd, 0, 0, wvTH, wvTL, Dd, 0, 0,
        nullptr, VpH, VpL, Dd, 0, 0, bv, Dd);

    // V^T per head (pairs)
    vt_pairs<<<dim3(Ss/32, HDIM/32, Bb*Hh), tblk>>>(VpH, VpL, VtH, VtL);

    // scores = QK^T/8 + mask -> fp32 S
    gemm_ps<128,2,0,0><<<dim3(Ss/128, Ss/128, Bb*Hh), 256, DSZ128>>>(
        QpH, QpL, Dd, (long long)Ss*Dd, HDIM,
        KpH, KpL, Dd, (long long)Ss*Dd, HDIM,
        S, nullptr, nullptr, Ss, 16LL*Ss*Ss, (long long)Ss*Ss,
        mask, HDIM);

    // softmax -> attn_weights mirror + single-plane fp16 P
    softmax_kernel<<<Bb*Hh*Ss, 256>>>(S, attn_ext, Ph);

    // context = P @ V -> pairs (A = single fp16 plane)
    gemm_ps<64,3,1,2><<<dim3(1, Ss/128, Bb*Hh), 256, DSZ64A>>>(
        Ph, nullptr, Ss, 16LL*Ss*Ss, (long long)Ss*Ss,
        VtH, VtL, Ss, 16LL*HDIM*Ss, (long long)HDIM*Ss,
        nullptr, cxH, cxL, Dd, (long long)Ss*Dd, HDIM,
        nullptr, Ss);

    // O-projection -> fp32 X
    gemm_ps<128,0,0,0><<<dim3(Dd/128, Mm/128, 1), 256, DSZ128>>>(
        cxH, cxL, Dd, 0, 0, woTH, woTL, Dd, 0, 0,
        X, nullptr, nullptr, Dd, 0, 0, bo, Dd);

    // Double LayerNorm -> attn_out fp32 + pairs
    ln_a_kernel<<<Mm, 256>>>(X, query, ln_mha_g, ln_mha_b,
                             ln_attn_g, ln_attn_b, ao, aoH, aoL);

    // FFN1 -> F pairs (relu)
    gemm_ps<128,1,1,0><<<dim3(Ff/128, Mm/128, 1), 256, DSZ128>>>(
        aoH, aoL, Dd, 0, 0, w1TH, w1TL, Dd, 0, 0,
        nullptr, FpH, FpL, Ff, 0, 0, b1, Dd);

    // FFN2 -> fp32 Z
    gemm_ps<128,0,0,0><<<dim3(Dd/128, Mm/128, 1), 256, DSZ128>>>(
        FpH, FpL, Ff, 0, 0, w2TH, w2TL, Ff, 0, 0,
        Z, nullptr, nullptr, Dd, 0, 0, b2, Ff);

    // Final LayerNorm -> main output
    ln_b_kernel<<<Mm, 256>>>(Z, ao, ln_ffn_g, ln_ffn_b, out);
}